// round 9
// baseline (speedup 1.0000x reference)
#include <cuda_runtime.h>
#include <cuda_fp16.h>
#include <cstdint>

// Problem dims (fixed)
#define FDIM 1024
#define CDIM 128
#define BDIM 2048

#define BM 32
#define BN 64
#define THREADS 512

// ---------------- scratch ----------------
__device__ __half g_b[CDIM * FDIM];   // softmax(w) fp16, [c][k] k-major

// ---------------- helpers ----------------
__device__ __forceinline__ uint32_t smem_u32(const void* p) {
    uint32_t a;
    asm("{ .reg .u64 t; cvta.to.shared.u64 t, %1; cvt.u32.u64 %0, t; }" : "=r"(a) : "l"(p));
    return a;
}
// full-K row (2048B pitch), 16B-granularity XOR swizzle within 128B
__device__ __forceinline__ uint32_t swzP(uint32_t row, uint32_t colByte) {
    return row * 2048u + (colByte ^ ((row & 7u) << 4));
}
#define CP_ASYNC16(sm, g) asm volatile("cp.async.cg.shared.global [%0], [%1], 16;" :: "r"(sm), "l"(g) : "memory")
#define CP_COMMIT()       asm volatile("cp.async.commit_group;" ::: "memory")
#define CP_WAITN(n)       asm volatile("cp.async.wait_group %0;" :: "n"(n) : "memory")

#define LDMATRIX_X4(r0, r1, r2, r3, addr)                                        \
    asm volatile("ldmatrix.sync.aligned.m8n8.x4.shared.b16 {%0,%1,%2,%3}, [%4];" \
                 : "=r"(r0), "=r"(r1), "=r"(r2), "=r"(r3) : "r"(addr))

#define MMA_F16(d, a, b)                                                         \
    asm volatile("mma.sync.aligned.m16n8k16.row.col.f32.f16.f16.f32 "            \
                 "{%0,%1,%2,%3}, {%4,%5,%6,%7}, {%8,%9}, {%0,%1,%2,%3};"         \
                 : "+f"((d)[0]), "+f"((d)[1]), "+f"((d)[2]), "+f"((d)[3])        \
                 : "r"((a)[0]), "r"((a)[1]), "r"((a)[2]), "r"((a)[3]),           \
                   "r"((b)[0]), "r"((b)[1]))

// ---------------------------------------------------------------------------
// Kernel 1: warp-per-class softmax(weight) -> g_b fp16 (shfl-only)
// ---------------------------------------------------------------------------
__global__ void __launch_bounds__(256) prep_w_kernel(const float* __restrict__ w) {
    const int gw   = (blockIdx.x * 256 + threadIdx.x) >> 5;   // class 0..127
    const int lane = threadIdx.x & 31;
    const float* row = w + (size_t)gw * FDIM;

    float4 v[8];
    float m = -1e30f;
#pragma unroll
    for (int j = 0; j < 8; j++) {
        v[j] = *reinterpret_cast<const float4*>(row + j * 128 + lane * 4);
        m = fmaxf(m, fmaxf(fmaxf(v[j].x, v[j].y), fmaxf(v[j].z, v[j].w)));
    }
#pragma unroll
    for (int s = 16; s > 0; s >>= 1) m = fmaxf(m, __shfl_xor_sync(0xffffffffu, m, s));

    float sum = 0.0f;
#pragma unroll
    for (int j = 0; j < 8; j++) {
        v[j].x = __expf(v[j].x - m); v[j].y = __expf(v[j].y - m);
        v[j].z = __expf(v[j].z - m); v[j].w = __expf(v[j].w - m);
        sum += (v[j].x + v[j].y) + (v[j].z + v[j].w);
    }
#pragma unroll
    for (int s = 16; s > 0; s >>= 1) sum += __shfl_xor_sync(0xffffffffu, sum, s);
    const float inv = 1.0f / sum;

#pragma unroll
    for (int j = 0; j < 8; j++) {
        __half2 h01 = __floats2half2_rn(v[j].x * inv, v[j].y * inv);
        __half2 h23 = __floats2half2_rn(v[j].z * inv, v[j].w * inv);
        uint2 pv = make_uint2(*reinterpret_cast<uint32_t*>(&h01),
                              *reinterpret_cast<uint32_t*>(&h23));
        *reinterpret_cast<uint2*>(g_b + (size_t)gw * FDIM + j * 128 + lane * 4) = pv;
    }
}

// ---------------------------------------------------------------------------
// Kernel 2: one-shot-resident GEMM. grid = 64 Mgroups x 2 Nhalves = 128 CTAs,
// 512 threads (16 warps). B-half (64x1024 fp16, 128KB) loaded ONCE via 8
// interleaved cp.async groups; A (32x1024) = LDG x -> exp -> fp16 STS, once.
// Warps 0-7:  K[0,512),  warp tile 16x16 over (32x64): wm=w>>2, wn=w&3.
// Warps 8-15: K[512,1024), same tiles. 4 wait+sync pairs gate the mainloop.
// Epilogue: hi warps STS partials -> lo warps add + log + store.
// ---------------------------------------------------------------------------
#define A_OFF   0                  // 64KB
#define B_OFF   65536              // 128KB
#define RED_OFF 196608             // 8KB
#define SMEM_TOTAL 204800

__global__ void __launch_bounds__(THREADS) mma_kernel(const float* __restrict__ x,
                                                      float* __restrict__ out) {
    extern __shared__ char smem[];
    const uint32_t sbase = smem_u32(smem);
    const int tid  = threadIdx.x;
    const int warp = tid >> 5;
    const int lane = tid & 31;

    const int mgroup = (int)blockIdx.x >> 1;   // 0..63
    const int nhalf  = (int)blockIdx.x & 1;    // 0..1

    // ---- issue all B cp.async groups, K-interleaved [0,4,1,5,2,6,3,7] ----
    const __half* bsrc = g_b + (size_t)nhalf * BN * FDIM;
    {
        const uint32_t row = (uint32_t)tid >> 4;        // 0..31 (x2 via t)
        const uint32_t c16 = (uint32_t)tid & 15;
#pragma unroll
        for (int gi = 0; gi < 8; gi++) {
            const int kc = (gi >> 1) + (gi & 1) * 4;    // 0,4,1,5,2,6,3,7
#pragma unroll
            for (int t = 0; t < 2; t++) {
                const uint32_t r = row + t * 32;        // 0..63
                CP_ASYNC16(sbase + B_OFF + swzP(r, (uint32_t)kc * 256 + c16 * 16),
                           bsrc + (size_t)r * FDIM + kc * 128 + c16 * 8);
            }
            CP_COMMIT();
        }
    }

    // ---- A: LDG x fp32 (full K), exp, STS fp16 (overlaps B flight) ----
    {
        const float* xbase = x + (size_t)mgroup * BM * FDIM;
        const uint32_t row = (uint32_t)tid >> 4;        // 0..31
        const uint32_t c4b = (uint32_t)tid & 15;        // float4 base col
        float4 v[16];
#pragma unroll
        for (int j = 0; j < 16; j++)
            v[j] = *reinterpret_cast<const float4*>(xbase + (size_t)row * FDIM + (c4b + j * 16) * 4);
#pragma unroll
        for (int j = 0; j < 16; j++) {
            __half2 h01 = __floats2half2_rn(__expf(v[j].x), __expf(v[j].y));
            __half2 h23 = __floats2half2_rn(__expf(v[j].z), __expf(v[j].w));
            uint2 pv = make_uint2(*reinterpret_cast<uint32_t*>(&h01),
                                  *reinterpret_cast<uint32_t*>(&h23));
            const uint32_t c4 = c4b + j * 16;
            const uint32_t addr = swzP(row, (c4 >> 1) * 16) + (c4 & 1) * 8;
            *reinterpret_cast<uint2*>(smem + A_OFF + addr) = pv;
        }
    }

    // ---- mainloop: 4 pairs, each gating K-chunk i (lo) and 4+i (hi) ----
    const int wm = (warp >> 2) & 1;
    const int wn = warp & 3;
    const int khalf = warp >> 3;                 // 0 = K[0,512), 1 = K[512,1024)

    float acc[2][2][4];                          // [parity][ni]
#pragma unroll
    for (int p = 0; p < 2; p++)
#pragma unroll
        for (int j = 0; j < 2; j++)
#pragma unroll
            for (int e = 0; e < 4; e++) acc[p][j][e] = 0.0f;

    const uint32_t aRow = wm * 16 + (lane & 7) + ((lane >> 3) & 1) * 8;
    const uint32_t aCol = (lane >> 4) * 16;
    const uint32_t bRow = wn * 16 + ((lane >> 4) & 1) * 8 + (lane & 7);
    const uint32_t bCol = ((lane >> 3) & 1) * 16;

#pragma unroll
    for (int i = 0; i < 4; i++) {
        switch (i) {   // wait until commits 0..2i+1 done (<= 6-2i pending)
            case 0: CP_WAITN(6); break;
            case 1: CP_WAITN(4); break;
            case 2: CP_WAITN(2); break;
            default: CP_WAITN(0); break;
        }
        __syncthreads();

        const int kc = khalf * 4 + i;            // this warp's K-chunk
#pragma unroll
        for (int ks = 0; ks < 8; ks++) {
            const uint32_t kb = (uint32_t)(kc * 8 + ks) * 32;
            uint32_t a[4], b[4];
            LDMATRIX_X4(a[0], a[1], a[2], a[3], sbase + A_OFF + swzP(aRow, kb + aCol));
            LDMATRIX_X4(b[0], b[1], b[2], b[3], sbase + B_OFF + swzP(bRow, kb + bCol));
            const int p = ks & 1;
            MMA_F16(acc[p][0], a, b);
            MMA_F16(acc[p][1], a, b + 2);
        }
    }

    // ---- epilogue: hi warps publish partials, lo warps combine+log+store ----
    float s[2][4];
#pragma unroll
    for (int j = 0; j < 2; j++)
#pragma unroll
        for (int e = 0; e < 4; e++) s[j][e] = acc[0][j][e] + acc[1][j][e];

    float* red = reinterpret_cast<float*>(smem + RED_OFF);
    if (khalf == 1) {
        float* dst = red + (size_t)(warp & 7) * 256 + lane * 8;
#pragma unroll
        for (int j = 0; j < 2; j++) {
            dst[j * 4 + 0] = s[j][0]; dst[j * 4 + 1] = s[j][1];
            dst[j * 4 + 2] = s[j][2]; dst[j * 4 + 3] = s[j][3];
        }
    }
    __syncthreads();
    if (khalf == 0) {
        const float* src = red + (size_t)warp * 256 + lane * 8;
#pragma unroll
        for (int j = 0; j < 2; j++) {
            const float t0 = s[j][0] + src[j * 4 + 0];
            const float t1 = s[j][1] + src[j * 4 + 1];
            const float t2 = s[j][2] + src[j * 4 + 2];
            const float t3 = s[j][3] + src[j * 4 + 3];
            const int m = mgroup * BM + wm * 16 + (lane >> 2);
            const int n = nhalf * BN + wn * 16 + j * 8 + (lane & 3) * 2;
            *reinterpret_cast<float2*>(out + (size_t)m * CDIM + n) =
                make_float2(__logf(t0), __logf(t1));
            *reinterpret_cast<float2*>(out + (size_t)(m + 8) * CDIM + n) =
                make_float2(__logf(t2), __logf(t3));
        }
    }
}

// ---------------------------------------------------------------------------
extern "C" void kernel_launch(void* const* d_in, const int* in_sizes, int n_in,
                              void* d_out, int out_size) {
    const float* x = (const float*)d_in[0];
    const float* w = (const float*)d_in[1];
    if (n_in >= 2 && in_sizes[0] == CDIM * FDIM && in_sizes[1] == BDIM * FDIM) {
        w = (const float*)d_in[0];
        x = (const float*)d_in[1];
    }
    float* out = (float*)d_out;

    static bool attr_set = false;
    if (!attr_set) {
        cudaFuncSetAttribute(mma_kernel, cudaFuncAttributeMaxDynamicSharedMemorySize, SMEM_TOTAL);
        attr_set = true;
    }

    prep_w_kernel<<<CDIM / 8, 256>>>(w);
    mma_kernel<<<(BDIM / BM) * (CDIM / BN), THREADS, SMEM_TOTAL>>>(x, out);
}